// round 15
// baseline (speedup 1.0000x reference)
#include <cuda_runtime.h>
#include <cuda_bf16.h>
#include <math.h>

#define BB 4
#define HH 512
#define WW 512
#define NPIX (BB*HH*WW)
#define TW 32
#define TH 8

#define TAUc   0.01f
#define RHOc   1.99f
#define SIGMAc 1.3888888888888888f   // 1/0.01/72

// Packed state:
//   g_s  [i] = { x2 (fp32 bits),  r2  (bf16x2) }
//   g_xr [i] = { xbar (fp32 bits), rbar (bf16x2) }
//   g_u2 [i] = u2 as 4x bf16 (uint2)
//   g_tmp[i] = TAU * eps2_adjoint(u2)  (fp32 float2), produced by k_B
typedef uint2 U2raw;
__device__ __align__(16) uint2  g_s  [NPIX];
__device__ __align__(16) uint2  g_xr [NPIX];
__device__ __align__(16) U2raw  g_u2 [NPIX];
__device__ __align__(16) float2 g_tmp[NPIX];

static __device__ __forceinline__ float4 u2unpack(U2raw r) {
    float2 f0 = __bfloat1622float2(*reinterpret_cast<__nv_bfloat162*>(&r.x));
    float2 f1 = __bfloat1622float2(*reinterpret_cast<__nv_bfloat162*>(&r.y));
    return make_float4(f0.x, f0.y, f1.x, f1.y);
}
static __device__ __forceinline__ float2 bf2unpack(unsigned r) {
    return __bfloat1622float2(*reinterpret_cast<__nv_bfloat162*>(&r));
}
static __device__ __forceinline__ unsigned bf2pack(float a, float b) {
    __nv_bfloat162 p = __floats2bfloat162_rn(a, b);
    return *reinterpret_cast<unsigned*>(&p);
}
static __device__ __forceinline__ U2raw u2pack(float a, float b, float c, float d) {
    U2raw r; r.x = bf2pack(a, b); r.y = bf2pack(c, d); return r;
}

// ---------------------------------------------------------------------------
// Kernel A (pointwise + tmp stencil, 2-row coarsened, PDL): the u2 stencil is
// gone — k_B precomputed g_tmp. Dependent section: 5 tmp loads + prox math.
// ---------------------------------------------------------------------------
template<bool LAST>
__global__ void __launch_bounds__(256)
k_A(const float* __restrict__ y, const int* __restrict__ ths,
    float* __restrict__ outx) {
    const int w = blockIdx.x * 32 + threadIdx.x;
    const int h = (blockIdx.y * 8 + threadIdx.y) * 2;      // even, <= 510
    const int b = blockIdx.z;
    const int i = (b * HH + h) * WW + w;

    // ---- prologue: independent of the immediately-prior kernel ----
    const uint2 s0 = __ldg(&g_s[i]);
    const uint2 s1 = __ldg(&g_s[i + WW]);
    const float x2o0 = __uint_as_float(s0.x);
    const float x2o1 = __uint_as_float(s1.x);
    const float yv0  = __ldg(&y[i]);
    const float yv1  = __ldg(&y[i + WW]);
    float lam1 = 1.f;
    if (!LAST) lam1 = 0.1f * (float)__ldg(ths);

    cudaGridDependencySynchronize();

    // ---- dependent: tmp (written by prior k_B) ----
    const float2* tp = g_tmp + i;
    const float2 tc0 = __ldg(tp);
    const float2 tc1 = __ldg(tp + WW);
    float t1u0 = 0.f;
    if (h > 0) t1u0 = __ldg(&(tp - WW)->y);
    float t0l0 = 0.f, t0l1 = 0.f;
    if (w > 0) {
        t0l0 = __ldg(&(tp - 1)->x);
        t0l1 = __ldg(&(tp + WW - 1)->x);
    }

    float dv0 = -tc0.y + t1u0 + t0l0;       // h < 511 always (h even <= 510)
    if (w < WW - 1) dv0 -= tc0.x;

    float dv1 = tc0.y + t0l1;               // h+1 > 0 always
    if (w < WW - 1)  dv1 -= tc1.x;
    if (h + 2 < HH)  dv1 -= tc1.y;

    const float inv = 1.f / (1.f + TAUc);
    const float x0 = (x2o0 - dv0 + TAUc * yv0) * inv;
    const float x1 = (x2o1 - dv1 + TAUc * yv1) * inv;
    const float x2n0 = x2o0 + RHOc * (x0 - x2o0);
    const float x2n1 = x2o1 + RHOc * (x1 - x2o1);

    if (LAST) {
        outx[i]      = x2n0;
        outx[i + WW] = x2n1;
        cudaTriggerProgrammaticLaunchCompletion();
        return;
    }

    const float itl = 1.f / (TAUc * lam1);
    uint2 xr0, xr1, sn0, sn1;
    xr0.x = __float_as_uint(2.f * x0 - x2o0);
    xr1.x = __float_as_uint(2.f * x1 - x2o1);
    sn0.x = __float_as_uint(x2n0);
    sn1.x = __float_as_uint(x2n1);
    {
        const float2 o = bf2unpack(s0.y);
        const float rvx = o.x + tc0.x, rvy = o.y + tc0.y;
        const float s = 1.f - 1.f / fmaxf(sqrtf(rvx*rvx + rvy*rvy) * itl, 1.f);
        const float rx = rvx * s, ry = rvy * s;
        xr0.y = bf2pack(2.f * rx - o.x, 2.f * ry - o.y);
        sn0.y = bf2pack(o.x + RHOc * (rx - o.x), o.y + RHOc * (ry - o.y));
    }
    {
        const float2 o = bf2unpack(s1.y);
        const float rvx = o.x + tc1.x, rvy = o.y + tc1.y;
        const float s = 1.f - 1.f / fmaxf(sqrtf(rvx*rvx + rvy*rvy) * itl, 1.f);
        const float rx = rvx * s, ry = rvy * s;
        xr1.y = bf2pack(2.f * rx - o.x, 2.f * ry - o.y);
        sn1.y = bf2pack(o.x + RHOc * (rx - o.x), o.y + RHOc * (ry - o.y));
    }
    g_xr[i]      = xr0;
    g_xr[i + WW] = xr1;
    g_s[i]       = sn0;
    g_s[i + WW]  = sn1;
    cudaTriggerProgrammaticLaunchCompletion();
}

// ---------------------------------------------------------------------------
// Kernel B (PDL): xbar/rbar halo -> v (12x34) -> u' recomputed on a 10x33
// ring (stored to g_u2 in-tile) -> tmp = TAU*eps2_adjoint(u2') per tile pixel
// (computed from the bf16-ROUNDED u' words => bitwise-equal to reading u2
// from global). FIRST: xbar==y, rbar==0, u2==0; also initializes g_s.
// Frames (image coords of [R][C]):
//   sx/srb [13][35]: (h0+R-2, w0+C-1)
//   sv     [12][34]: (h0+R-2, w0+C-1)
//   su2/spu[10][33]: (h0+R-1, w0+C)
// ---------------------------------------------------------------------------
template<bool FIRST>
__global__ void __launch_bounds__(256)
k_B(const float* __restrict__ y, const int* __restrict__ ths) {
    __shared__ float    sx [13][36];
    __shared__ unsigned srb[13][36];
    __shared__ float2   sv [12][35];
    __shared__ uint2    su2[10][33];
    __shared__ uint2    spu[10][33];

    const int tx = threadIdx.x, ty = threadIdx.y;
    const int tid = ty * TW + tx;
    const int w0 = blockIdx.x * TW, h0 = blockIdx.y * TH, b = blockIdx.z;
    const int boff = b * HH * WW;

    // ---- prologue: old u2 region (written 2 launches back) + ths ----
    const float lam2 = 0.15f * (float)__ldg(ths);
    if (!FIRST) {
        #pragma unroll
        for (int idx = tid; idx < 10 * 33; idx += 256) {
            int R = idx / 33, C = idx % 33;
            int gh = h0 + R - 1, gw = w0 + C;
            uint2 v = make_uint2(0u, 0u);
            if ((unsigned)gh < HH && (unsigned)gw < WW)
                v = __ldg(&g_u2[boff + gh * WW + gw]);
            su2[R][C] = v;
        }
    }

    cudaGridDependencySynchronize();

    // ---- xbar/rbar halo (from prior k_A) ----
    #pragma unroll
    for (int idx = tid; idx < 13 * 35; idx += 256) {
        int R = idx / 35, C = idx % 35;
        int gh = h0 + R - 2, gw = w0 + C - 1;
        float xv = 0.f;
        unsigned rb = 0u;
        if ((unsigned)gh < HH && (unsigned)gw < WW) {
            if (FIRST) {
                xv = __ldg(&y[boff + gh * WW + gw]);
            } else {
                uint2 pw = __ldg(&g_xr[boff + gh * WW + gw]);
                xv = __uint_as_float(pw.x);
                rb = pw.y;
            }
        }
        sx[R][C]  = xv;
        srb[R][C] = rb;
    }
    __syncthreads();

    // ---- v = nabla2(xbar) - rbar on 12x34 ----
    #pragma unroll
    for (int idx = tid; idx < 12 * 34; idx += 256) {
        int R = idx / 34, C = idx % 34;
        int gh = h0 + R - 2, gw = w0 + C - 1;
        float2 v = make_float2(0.f, 0.f);
        if ((unsigned)gh < HH && (unsigned)gw < WW) {
            float xc = sx[R][C];
            float v0 = (gw < WW - 1) ? (sx[R][C + 1] - xc) : 0.f;
            float v1 = (gh < HH - 1) ? (sx[R + 1][C] - xc) : 0.f;
            float2 rb = bf2unpack(srb[R][C]);
            v = make_float2(v0 - rb.x, v1 - rb.y);
        }
        sv[R][C] = v;
    }
    __syncthreads();

    // ---- u' on the 10x33 ring; store to g_u2 for in-tile pixels ----
    #pragma unroll
    for (int idx = tid; idx < 10 * 33; idx += 256) {
        int R = idx / 33, C = idx % 33;
        int gh = h0 + R - 1, gw = w0 + C;
        uint2 up = make_uint2(0u, 0u);
        if ((unsigned)gh < HH && (unsigned)gw < WW) {
            float2 vc = sv[R + 1][C + 1];
            float2 vu = sv[R][C + 1];
            float2 vl = sv[R + 1][C];
            float2 vd = sv[R + 2][C + 1];
            float G0 = vc.x - vu.x;
            float G1 = (gw > 0) ? (vc.x - vl.x) : 0.f;
            float G2 = vc.y - vl.y;
            float G3 = (gh < HH - 1) ? (vd.y - vc.y) : 0.f;
            float4 o = FIRST ? make_float4(0.f, 0.f, 0.f, 0.f)
                             : u2unpack(su2[R][C]);
            float u0 = o.x + SIGMAc * G0;
            float u1 = o.y + SIGMAc * G1;
            float u2c = o.z + SIGMAc * G2;
            float u3 = o.w + SIGMAc * G3;
            float nrm = sqrtf(u0*u0 + u1*u1 + u2c*u2c + u3*u3);
            float sc = 1.f / fmaxf(nrm * (1.f / lam2), 1.f);
            up = u2pack(o.x + RHOc * (u0  * sc - o.x),
                        o.y + RHOc * (u1  * sc - o.y),
                        o.z + RHOc * (u2c * sc - o.z),
                        o.w + RHOc * (u3  * sc - o.w));
            if (R >= 1 && R < 9 && C < 32)
                g_u2[boff + gh * WW + gw] = up;
        }
        spu[R][C] = up;
    }
    __syncthreads();

    // ---- tmp = TAU*eps2_adjoint(u2') per tile pixel (from ROUNDED words) ----
    {
        const int R = ty + 1, C = tx;
        const int gi = boff + (h0 + ty) * WW + (w0 + tx);
        const float4 ac = u2unpack(spu[R][C]);
        const float4 ad = u2unpack(spu[R + 1][C]);
        const float4 ar = u2unpack(spu[R][C + 1]);
        const float  auw = bf2unpack(spu[R - 1][C].y).y;
        const float tmp0 = TAUc * (ac.x - ad.x - ar.y + ac.y);
        const float tmp1 = TAUc * (ac.z - ar.z - ac.w + auw);
        g_tmp[gi] = make_float2(tmp0, tmp1);
        if (FIRST) {
            uint2 s;
            s.x = __float_as_uint(sx[ty + 2][tx + 1]);
            s.y = 0u;
            g_s[gi] = s;
        }
    }
    cudaTriggerProgrammaticLaunchCompletion();
}

// ---------------------------------------------------------------------------
// Host side: PDL launches on the default (capture) stream.
// ---------------------------------------------------------------------------
static void launch_pdl_A(void (*fn)(const float*, const int*, float*),
                         dim3 g, dim3 blk,
                         const float* y, const int* ths, float* out) {
    cudaLaunchConfig_t cfg = {};
    cfg.gridDim = g;
    cfg.blockDim = blk;
    cfg.dynamicSmemBytes = 0;
    cfg.stream = 0;
    cudaLaunchAttribute attr[1];
    attr[0].id = cudaLaunchAttributeProgrammaticStreamSerialization;
    attr[0].val.programmaticStreamSerializationAllowed = 1;
    cfg.attrs = attr;
    cfg.numAttrs = 1;
    cudaLaunchKernelEx(&cfg, fn, y, ths, out);
}
static void launch_pdl_B(void (*fn)(const float*, const int*), dim3 g, dim3 blk,
                         const float* y, const int* ths) {
    cudaLaunchConfig_t cfg = {};
    cfg.gridDim = g;
    cfg.blockDim = blk;
    cfg.dynamicSmemBytes = 0;
    cfg.stream = 0;
    cudaLaunchAttribute attr[1];
    attr[0].id = cudaLaunchAttributeProgrammaticStreamSerialization;
    attr[0].val.programmaticStreamSerializationAllowed = 1;
    cfg.attrs = attr;
    cfg.numAttrs = 1;
    cudaLaunchKernelEx(&cfg, fn, y, ths);
}

extern "C" void kernel_launch(void* const* d_in, const int* in_sizes, int n_in,
                              void* d_out, int out_size) {
    const float* y   = (const float*)d_in[0];
    const int*   ths = (const int*)d_in[1];
    float*       out = (float*)d_out;

    dim3 blkA(32, 8, 1);
    dim3 grdA(WW / 32, HH / 16, BB);     // 2 rows per thread
    dim3 blkB(TW, TH, 1);
    dim3 grdB(WW / TW, HH / TH, BB);

    // Iteration 1 (specialized: A is a no-op closed form)
    launch_pdl_B(k_B<true>, grdB, blkB, y, ths);

    // Iterations 2..9
    for (int it = 1; it < 9; ++it) {
        launch_pdl_A(k_A<false>, grdA, blkA, y, ths, nullptr);
        launch_pdl_B(k_B<false>, grdB, blkB, y, ths);
    }

    // Iteration 10: only the x path matters; write straight to output.
    launch_pdl_A(k_A<true>, grdA, blkA, y, ths, out);
}

// round 16
// speedup vs baseline: 1.2381x; 1.2381x over previous
#include <cuda_runtime.h>
#include <cuda_bf16.h>
#include <math.h>

#define BB 4
#define HH 512
#define WW 512
#define NPIX (BB*HH*WW)
#define TW 32
#define TH 8

#define TAUc   0.01f
#define RHOc   1.99f
#define SIGMAc 1.3888888888888888f   // 1/0.01/72

// Packed state:
//   g_sxr[i] = { x2 (fp32 bits), r2 (bf16x2), xbar (fp32 bits), rbar (bf16x2) }
//   g_u2 [i] = u2 as 4x bf16 (uint2)
typedef uint2 U2raw;
__device__ __align__(16) uint4 g_sxr[NPIX];
__device__ __align__(16) U2raw g_u2 [NPIX];

static __device__ __forceinline__ float4 u2unpack(U2raw r) {
    float2 f0 = __bfloat1622float2(*reinterpret_cast<__nv_bfloat162*>(&r.x));
    float2 f1 = __bfloat1622float2(*reinterpret_cast<__nv_bfloat162*>(&r.y));
    return make_float4(f0.x, f0.y, f1.x, f1.y);
}
static __device__ __forceinline__ float2 bf2unpack(unsigned r) {
    return __bfloat1622float2(*reinterpret_cast<__nv_bfloat162*>(&r));
}
static __device__ __forceinline__ unsigned bf2pack(float a, float b) {
    __nv_bfloat162 p = __floats2bfloat162_rn(a, b);
    return *reinterpret_cast<unsigned*>(&p);
}
static __device__ __forceinline__ U2raw u2pack(float a, float b, float c, float d) {
    U2raw r; r.x = bf2pack(a, b); r.y = bf2pack(c, d); return r;
}

// ---------------------------------------------------------------------------
// Kernel A (2-row coarsened, uint4 state, PDL): prologue loads g_sxr/y/ths
// (x2/r2 fields written 2 launches back -> transitively visible), waits,
// then the u2 stencil (written by the prior k_B).
// ---------------------------------------------------------------------------
template<bool LAST>
__global__ void __launch_bounds__(256)
k_A(const float* __restrict__ y, const int* __restrict__ ths,
    float* __restrict__ outx) {
    const int w = blockIdx.x * 32 + threadIdx.x;
    const int h = (blockIdx.y * 8 + threadIdx.y) * 2;      // even, <= 510
    const int b = blockIdx.z;
    const int i = (b * HH + h) * WW + w;
    const U2raw* p0 = g_u2 + b * HH * WW + h * WW + w;

    // ---- prologue: independent of the immediately-prior kernel ----
    const uint4 s0 = __ldg(&g_sxr[i]);
    const uint4 s1 = __ldg(&g_sxr[i + WW]);
    const float x2o0 = __uint_as_float(s0.x);
    const float x2o1 = __uint_as_float(s1.x);
    const float yv0  = __ldg(&y[i]);
    const float yv1  = __ldg(&y[i + WW]);
    float lam1 = 1.f;
    if (!LAST) lam1 = 0.1f * (float)__ldg(ths);

    cudaGridDependencySynchronize();

    // ---- dependent: u2 (written by prior k_B) ----
    const uint2 w0c = __ldg(p0);
    const uint2 w1c = __ldg(p0 + WW);
    float2 c0xy = bf2unpack(w0c.x), c0zw = bf2unpack(w0c.y);
    float2 c1xy = bf2unpack(w1c.x), c1zw = bf2unpack(w1c.y);
    float2 r0xy = make_float2(0,0), r0zw = r0xy, r1xy = r0xy, r1zw = r0xy;
    if (w < WW - 1) {
        uint2 a = __ldg(p0 + 1), bb2 = __ldg(p0 + WW + 1);
        r0xy = bf2unpack(a.x); r0zw = bf2unpack(a.y);
        r1xy = bf2unpack(bb2.x); r1zw = bf2unpack(bb2.y);
    }
    float2 upzw = make_float2(0,0);
    if (h > 0) upzw = bf2unpack(__ldg(&(p0 - WW)->y));
    float2 l0 = make_float2(0,0), l1 = l0;
    if (w > 0) {
        l0 = bf2unpack(__ldg(&(p0 - 1)->x));
        l1 = bf2unpack(__ldg(&(p0 + WW - 1)->x));
    }
    float Xd1 = 0.f, Xdl1 = 0.f;
    if (h + 2 < HH) {
        Xd1 = bf2unpack(__ldg(&(p0 + 2 * WW)->x)).x;
        if (w > 0) Xdl1 = bf2unpack(__ldg(&(p0 + 2 * WW - 1)->x)).x;
    }
    float Zur0 = 0.f;
    if (h > 0 && w < WW - 1) Zur0 = bf2unpack(__ldg(&(p0 - WW + 1)->y)).x;
    float Wu20 = 0.f;
    if (h >= 2) Wu20 = bf2unpack(__ldg(&(p0 - 2 * WW)->y)).y;

    const float t0p0 = TAUc * (c0xy.x - c1xy.x - r0xy.y + c0xy.y);
    const float t1p0 = TAUc * (c0zw.x - r0zw.x - c0zw.y + upzw.y);
    const float t0l0 = TAUc * (l0.x - l1.x - c0xy.y + l0.y);
    const float t1u0 = TAUc * (upzw.x - Zur0 - upzw.y + Wu20);
    const float t0p1 = TAUc * (c1xy.x - Xd1 - r1xy.y + c1xy.y);
    const float t1p1 = TAUc * (c1zw.x - r1zw.x - c1zw.y + c0zw.y);
    const float t0l1 = TAUc * (l1.x - Xdl1 - c1xy.y + l1.y);

    float dv0 = -t1p0;                  // h < 511 always (h even <= 510)
    if (w < WW - 1) dv0 -= t0p0;
    if (w > 0)      dv0 += t0l0;
    if (h > 0)      dv0 += t1u0;

    float dv1 = t1p0;                   // h+1 > 0 always
    if (w < WW - 1)  dv1 -= t0p1;
    if (w > 0)       dv1 += t0l1;
    if (h + 2 < HH)  dv1 -= t1p1;

    const float inv = 1.f / (1.f + TAUc);
    const float x0 = (x2o0 - dv0 + TAUc * yv0) * inv;
    const float x1 = (x2o1 - dv1 + TAUc * yv1) * inv;
    const float x2n0 = x2o0 + RHOc * (x0 - x2o0);
    const float x2n1 = x2o1 + RHOc * (x1 - x2o1);

    if (LAST) {
        outx[i]      = x2n0;
        outx[i + WW] = x2n1;
        cudaTriggerProgrammaticLaunchCompletion();
        return;
    }

    const float itl = 1.f / (TAUc * lam1);
    uint4 n0, n1;
    n0.x = __float_as_uint(x2n0);
    n0.z = __float_as_uint(2.f * x0 - x2o0);
    n1.x = __float_as_uint(x2n1);
    n1.z = __float_as_uint(2.f * x1 - x2o1);
    {
        const float2 o = bf2unpack(s0.y);
        const float rvx = o.x + t0p0, rvy = o.y + t1p0;
        const float s = 1.f - 1.f / fmaxf(sqrtf(rvx*rvx + rvy*rvy) * itl, 1.f);
        const float rx = rvx * s, ry = rvy * s;
        n0.w = bf2pack(2.f * rx - o.x, 2.f * ry - o.y);
        n0.y = bf2pack(o.x + RHOc * (rx - o.x), o.y + RHOc * (ry - o.y));
    }
    {
        const float2 o = bf2unpack(s1.y);
        const float rvx = o.x + t0p1, rvy = o.y + t1p1;
        const float s = 1.f - 1.f / fmaxf(sqrtf(rvx*rvx + rvy*rvy) * itl, 1.f);
        const float rx = rvx * s, ry = rvy * s;
        n1.w = bf2pack(2.f * rx - o.x, 2.f * ry - o.y);
        n1.y = bf2pack(o.x + RHOc * (rx - o.x), o.y + RHOc * (ry - o.y));
    }
    g_sxr[i]      = n0;
    g_sxr[i + WW] = n1;
    cudaTriggerProgrammaticLaunchCompletion();
}

// ---------------------------------------------------------------------------
// Kernel B (PDL, uint4 xbar/rbar halo): one packed halo load feeds both the
// nabla2(xbar) stencil and the rbar subtraction. FIRST: xbar==y, rbar==0,
// u2==0; also initializes g_sxr = {y, 0, y, 0}.
// ---------------------------------------------------------------------------
template<bool FIRST>
__global__ void __launch_bounds__(TW*TH)
k_B(const float* __restrict__ y, const int* __restrict__ ths) {
    __shared__ float    sx [TH + 3][TW + 3];
    __shared__ unsigned srb[TH + 3][TW + 2];
    __shared__ float2   sv [TH + 2][TW + 2];

    const int tx = threadIdx.x, ty = threadIdx.y;
    const int tid = ty * TW + tx;
    const int w0 = blockIdx.x * TW, h0 = blockIdx.y * TH, b = blockIdx.z;
    const int boff = b * HH * WW;

    const int h = h0 + ty, w = w0 + tx;
    const int i = boff + h * WW + w;

    // ---- prologue ----
    float4 u2o = make_float4(0.f, 0.f, 0.f, 0.f);
    if (!FIRST) u2o = u2unpack(__ldg(&g_u2[i]));
    const float lam2 = 0.15f * (float)__ldg(ths);

    cudaGridDependencySynchronize();

    // ---- dependent: packed xbar/rbar halo (from prior k_A) ----
    #pragma unroll
    for (int idx = tid; idx < (TH + 3) * (TW + 2); idx += TW * TH) {
        int rr = idx / (TW + 2), cc = idx % (TW + 2);
        int gh = h0 + rr - 1, gw = w0 + cc - 1;
        float xv = 0.f;
        unsigned rb = 0u;
        if (gh >= 0 && gh < HH && gw >= 0 && gw < WW) {
            if (FIRST) {
                xv = __ldg(&y[boff + gh * WW + gw]);
            } else {
                uint4 pw = __ldg(&g_sxr[boff + gh * WW + gw]);
                xv = __uint_as_float(pw.z);
                rb = pw.w;
            }
        }
        sx[rr][cc]  = xv;
        srb[rr][cc] = rb;
    }
    __syncthreads();

    #pragma unroll
    for (int idx = tid; idx < (TH + 2) * (TW + 1); idx += TW * TH) {
        int R = idx / (TW + 1), C = idx % (TW + 1);
        int gh = h0 + R - 1, gw = w0 + C - 1;
        float2 v = make_float2(0.f, 0.f);
        if (gh >= 0 && gh < HH && gw >= 0 && gw < WW) {
            float xc = sx[R][C];
            float v0 = (gw < WW - 1) ? (sx[R][C + 1] - xc) : 0.f;
            float v1 = (gh < HH - 1) ? (sx[R + 1][C] - xc) : 0.f;
            float2 rb = bf2unpack(srb[R][C]);
            v = make_float2(v0 - rb.x, v1 - rb.y);
        }
        sv[R][C] = v;
    }
    __syncthreads();

    float2 vc = sv[ty + 1][tx + 1];
    float2 vu = sv[ty][tx + 1];
    float2 vl = sv[ty + 1][tx];
    float2 vd = sv[ty + 2][tx + 1];

    float G0 = vc.x - vu.x;
    float G1 = (w > 0) ? (vc.x - vl.x) : 0.f;
    float G2 = vc.y - vl.y;
    float G3 = (h < HH - 1) ? (vd.y - vc.y) : 0.f;

    float u0 = u2o.x + SIGMAc * G0;
    float u1 = u2o.y + SIGMAc * G1;
    float u2c = u2o.z + SIGMAc * G2;
    float u3 = u2o.w + SIGMAc * G3;

    float nrm = sqrtf(u0 * u0 + u1 * u1 + u2c * u2c + u3 * u3);
    float sc = 1.f / fmaxf(nrm * (1.f / lam2), 1.f);
    u0 *= sc; u1 *= sc; u2c *= sc; u3 *= sc;

    g_u2[i] = u2pack(u2o.x + RHOc * (u0  - u2o.x),
                     u2o.y + RHOc * (u1  - u2o.y),
                     u2o.z + RHOc * (u2c - u2o.z),
                     u2o.w + RHOc * (u3  - u2o.w));

    if (FIRST) {
        uint4 s;
        s.x = __float_as_uint(sx[ty + 1][tx + 1]);
        s.y = 0u;
        s.z = s.x;
        s.w = 0u;
        g_sxr[i] = s;
    }
    cudaTriggerProgrammaticLaunchCompletion();
}

// ---------------------------------------------------------------------------
// Host side: PDL launches on the default (capture) stream.
// ---------------------------------------------------------------------------
static void launch_pdl_A(void (*fn)(const float*, const int*, float*),
                         dim3 g, dim3 blk,
                         const float* y, const int* ths, float* out) {
    cudaLaunchConfig_t cfg = {};
    cfg.gridDim = g;
    cfg.blockDim = blk;
    cfg.dynamicSmemBytes = 0;
    cfg.stream = 0;
    cudaLaunchAttribute attr[1];
    attr[0].id = cudaLaunchAttributeProgrammaticStreamSerialization;
    attr[0].val.programmaticStreamSerializationAllowed = 1;
    cfg.attrs = attr;
    cfg.numAttrs = 1;
    cudaLaunchKernelEx(&cfg, fn, y, ths, out);
}
static void launch_pdl_B(void (*fn)(const float*, const int*), dim3 g, dim3 blk,
                         const float* y, const int* ths) {
    cudaLaunchConfig_t cfg = {};
    cfg.gridDim = g;
    cfg.blockDim = blk;
    cfg.dynamicSmemBytes = 0;
    cfg.stream = 0;
    cudaLaunchAttribute attr[1];
    attr[0].id = cudaLaunchAttributeProgrammaticStreamSerialization;
    attr[0].val.programmaticStreamSerializationAllowed = 1;
    cfg.attrs = attr;
    cfg.numAttrs = 1;
    cudaLaunchKernelEx(&cfg, fn, y, ths);
}

extern "C" void kernel_launch(void* const* d_in, const int* in_sizes, int n_in,
                              void* d_out, int out_size) {
    const float* y   = (const float*)d_in[0];
    const int*   ths = (const int*)d_in[1];
    float*       out = (float*)d_out;

    dim3 blkA(32, 8, 1);
    dim3 grdA(WW / 32, HH / 16, BB);     // 2 rows per thread
    dim3 blkB(TW, TH, 1);
    dim3 grdB(WW / TW, HH / TH, BB);

    // Iteration 1 (specialized: A is a no-op closed form)
    launch_pdl_B(k_B<true>, grdB, blkB, y, ths);

    // Iterations 2..9
    for (int it = 1; it < 9; ++it) {
        launch_pdl_A(k_A<false>, grdA, blkA, y, ths, nullptr);
        launch_pdl_B(k_B<false>, grdB, blkB, y, ths);
    }

    // Iteration 10: only the x path matters; write straight to output.
    launch_pdl_A(k_A<true>, grdA, blkA, y, ths, out);
}

// round 17
// speedup vs baseline: 1.3433x; 1.0849x over previous
#include <cuda_runtime.h>
#include <cuda_bf16.h>
#include <math.h>

#define BB 4
#define HH 512
#define WW 512
#define NPIX (BB*HH*WW)
#define TW 32
#define TH 8

// Padded plane geometry for guard-ring arrays (rows 128B-aligned):
#define PW 544             // padded width (elements)
#define BC 16              // base column offset (>=2 guard cols, keeps 128B align)
#define BR 2               // base row offset (2 guard rows top/bottom)
#define PHH 516            // padded height
#define PLANE (PW*PHH)

#define TAUc   0.01f
#define RHOc   1.99f
#define SIGMAc 1.3888888888888888f   // 1/0.01/72

// g_s  [i]          = { x2 (fp32 bits), r2 (bf16x2) }   (unpadded, NPIX)
// g_xrp[padded]     = { xbar (fp32 bits), rbar (bf16x2) }, zero guard ring
// g_u2p[padded]     = u2 as 4x bf16 (uint2), zero guard ring
// Guard rings are never written; __device__ globals are zero-initialized.
__device__ __align__(16) uint2 g_s  [NPIX];
__device__ __align__(16) uint2 g_xrp[BB*PLANE];
__device__ __align__(16) uint2 g_u2p[BB*PLANE];

static __device__ __forceinline__ float4 u2unpack(uint2 r) {
    float2 f0 = __bfloat1622float2(*reinterpret_cast<__nv_bfloat162*>(&r.x));
    float2 f1 = __bfloat1622float2(*reinterpret_cast<__nv_bfloat162*>(&r.y));
    return make_float4(f0.x, f0.y, f1.x, f1.y);
}
static __device__ __forceinline__ float2 bf2unpack(unsigned r) {
    return __bfloat1622float2(*reinterpret_cast<__nv_bfloat162*>(&r));
}
static __device__ __forceinline__ unsigned bf2pack(float a, float b) {
    __nv_bfloat162 p = __floats2bfloat162_rn(a, b);
    return *reinterpret_cast<unsigned*>(&p);
}
static __device__ __forceinline__ uint2 u2pack(float a, float b, float c, float d) {
    uint2 r; r.x = bf2pack(a, b); r.y = bf2pack(c, d); return r;
}

// ---------------------------------------------------------------------------
// Kernel A (2-row coarsened, PDL, unconditional padded u2 loads): prologue
// loads g_s/y/ths (written >= 2 launches back -> transitively visible),
// waits, then the u2 stencil from the padded plane.
// ---------------------------------------------------------------------------
template<bool LAST>
__global__ void __launch_bounds__(256)
k_A(const float* __restrict__ y, const int* __restrict__ ths,
    float* __restrict__ outx) {
    const int w = blockIdx.x * 32 + threadIdx.x;
    const int h = (blockIdx.y * 8 + threadIdx.y) * 2;      // even, <= 510
    const int b = blockIdx.z;
    const int i = (b * HH + h) * WW + w;
    const int ip = b * PLANE + (h + BR) * PW + (w + BC);
    const uint2* pp = g_u2p + ip;

    // ---- prologue: independent of the immediately-prior kernel ----
    const uint2 s0 = __ldg(&g_s[i]);
    const uint2 s1 = __ldg(&g_s[i + WW]);
    const float x2o0 = __uint_as_float(s0.x);
    const float x2o1 = __uint_as_float(s1.x);
    const float yv0  = __ldg(&y[i]);
    const float yv1  = __ldg(&y[i + WW]);
    float lam1 = 1.f;
    if (!LAST) lam1 = 0.1f * (float)__ldg(ths);

    cudaGridDependencySynchronize();

    // ---- dependent: u2 stencil (all unconditional; guard ring is zero) ----
    const uint2 w0c = __ldg(pp);
    const uint2 w1c = __ldg(pp + PW);
    const uint2 a   = __ldg(pp + 1);
    const uint2 bb2 = __ldg(pp + PW + 1);
    const float2 upzw = bf2unpack(__ldg(&(pp - PW)->y));
    const float2 l0   = bf2unpack(__ldg(&(pp - 1)->x));
    const float2 l1   = bf2unpack(__ldg(&(pp + PW - 1)->x));
    const float  Xd1  = bf2unpack(__ldg(&(pp + 2 * PW)->x)).x;
    const float  Xdl1 = bf2unpack(__ldg(&(pp + 2 * PW - 1)->x)).x;
    const float  Zur0 = bf2unpack(__ldg(&(pp - PW + 1)->y)).x;
    const float  Wu20 = bf2unpack(__ldg(&(pp - 2 * PW)->y)).y;

    const float2 c0xy = bf2unpack(w0c.x), c0zw = bf2unpack(w0c.y);
    const float2 c1xy = bf2unpack(w1c.x), c1zw = bf2unpack(w1c.y);
    const float2 r0xy = bf2unpack(a.x),   r0zw = bf2unpack(a.y);
    const float2 r1xy = bf2unpack(bb2.x), r1zw = bf2unpack(bb2.y);

    const float t0p0 = TAUc * (c0xy.x - c1xy.x - r0xy.y + c0xy.y);
    const float t1p0 = TAUc * (c0zw.x - r0zw.x - c0zw.y + upzw.y);
    const float t0l0 = TAUc * (l0.x - l1.x - c0xy.y + l0.y);
    const float t1u0 = TAUc * (upzw.x - Zur0 - upzw.y + Wu20);
    const float t0p1 = TAUc * (c1xy.x - Xd1 - r1xy.y + c1xy.y);
    const float t1p1 = TAUc * (c1zw.x - r1zw.x - c1zw.y + c0zw.y);
    const float t0l1 = TAUc * (l1.x - Xdl1 - c1xy.y + l1.y);

    float dv0 = -t1p0;                  // h < 511 always (h even <= 510)
    if (w < WW - 1) dv0 -= t0p0;
    if (w > 0)      dv0 += t0l0;
    if (h > 0)      dv0 += t1u0;

    float dv1 = t1p0;                   // h+1 > 0 always
    if (w < WW - 1)  dv1 -= t0p1;
    if (w > 0)       dv1 += t0l1;
    if (h + 2 < HH)  dv1 -= t1p1;

    const float inv = 1.f / (1.f + TAUc);
    const float x0 = (x2o0 - dv0 + TAUc * yv0) * inv;
    const float x1 = (x2o1 - dv1 + TAUc * yv1) * inv;
    const float x2n0 = x2o0 + RHOc * (x0 - x2o0);
    const float x2n1 = x2o1 + RHOc * (x1 - x2o1);

    if (LAST) {
        outx[i]      = x2n0;
        outx[i + WW] = x2n1;
        cudaTriggerProgrammaticLaunchCompletion();
        return;
    }

    const float itl = 1.f / (TAUc * lam1);
    uint2 xr0, xr1, sn0, sn1;
    xr0.x = __float_as_uint(2.f * x0 - x2o0);
    xr1.x = __float_as_uint(2.f * x1 - x2o1);
    sn0.x = __float_as_uint(x2n0);
    sn1.x = __float_as_uint(x2n1);
    {
        const float2 o = bf2unpack(s0.y);
        const float rvx = o.x + t0p0, rvy = o.y + t1p0;
        const float s = 1.f - 1.f / fmaxf(sqrtf(rvx*rvx + rvy*rvy) * itl, 1.f);
        const float rx = rvx * s, ry = rvy * s;
        xr0.y = bf2pack(2.f * rx - o.x, 2.f * ry - o.y);
        sn0.y = bf2pack(o.x + RHOc * (rx - o.x), o.y + RHOc * (ry - o.y));
    }
    {
        const float2 o = bf2unpack(s1.y);
        const float rvx = o.x + t0p1, rvy = o.y + t1p1;
        const float s = 1.f - 1.f / fmaxf(sqrtf(rvx*rvx + rvy*rvy) * itl, 1.f);
        const float rx = rvx * s, ry = rvy * s;
        xr1.y = bf2pack(2.f * rx - o.x, 2.f * ry - o.y);
        sn1.y = bf2pack(o.x + RHOc * (rx - o.x), o.y + RHOc * (ry - o.y));
    }
    g_xrp[ip]      = xr0;
    g_xrp[ip + PW] = xr1;
    g_s[i]         = sn0;
    g_s[i + WW]    = sn1;
    cudaTriggerProgrammaticLaunchCompletion();
}

// ---------------------------------------------------------------------------
// Kernel B (PDL, padded xbar/rbar halo — unconditional loads): one packed
// halo load feeds both nabla2(xbar) and the rbar subtraction. FIRST:
// xbar==y, rbar==0, u2==0; also initializes g_s = (y, 0).
// ---------------------------------------------------------------------------
template<bool FIRST>
__global__ void __launch_bounds__(TW*TH)
k_B(const float* __restrict__ y, const int* __restrict__ ths) {
    __shared__ float    sx [TH + 3][TW + 3];
    __shared__ unsigned srb[TH + 3][TW + 2];
    __shared__ float2   sv [TH + 2][TW + 2];

    const int tx = threadIdx.x, ty = threadIdx.y;
    const int tid = ty * TW + tx;
    const int w0 = blockIdx.x * TW, h0 = blockIdx.y * TH, b = blockIdx.z;
    const int boff = b * HH * WW;
    const int poff = b * PLANE;

    const int h = h0 + ty, w = w0 + tx;
    const int i = boff + h * WW + w;
    const int ip = poff + (h + BR) * PW + (w + BC);

    // ---- prologue ----
    float4 u2o = make_float4(0.f, 0.f, 0.f, 0.f);
    if (!FIRST) u2o = u2unpack(__ldg(&g_u2p[ip]));
    const float lam2 = 0.15f * (float)__ldg(ths);

    cudaGridDependencySynchronize();

    // ---- dependent: packed xbar/rbar halo (unconditional for !FIRST) ----
    #pragma unroll
    for (int idx = tid; idx < (TH + 3) * (TW + 2); idx += TW * TH) {
        int rr = idx / (TW + 2), cc = idx % (TW + 2);
        int gh = h0 + rr - 1, gw = w0 + cc - 1;
        float xv = 0.f;
        unsigned rb = 0u;
        if (FIRST) {
            if (gh >= 0 && gh < HH && gw >= 0 && gw < WW)
                xv = __ldg(&y[boff + gh * WW + gw]);
        } else {
            uint2 pw = __ldg(&g_xrp[poff + (gh + BR) * PW + (gw + BC)]);
            xv = __uint_as_float(pw.x);
            rb = pw.y;
        }
        sx[rr][cc]  = xv;
        srb[rr][cc] = rb;
    }
    __syncthreads();

    #pragma unroll
    for (int idx = tid; idx < (TH + 2) * (TW + 1); idx += TW * TH) {
        int R = idx / (TW + 1), C = idx % (TW + 1);
        int gh = h0 + R - 1, gw = w0 + C - 1;
        float2 v = make_float2(0.f, 0.f);
        if ((unsigned)gh < HH && (unsigned)gw < WW) {
            float xc = sx[R][C];
            float v0 = (gw < WW - 1) ? (sx[R][C + 1] - xc) : 0.f;
            float v1 = (gh < HH - 1) ? (sx[R + 1][C] - xc) : 0.f;
            float2 rb = bf2unpack(srb[R][C]);
            v = make_float2(v0 - rb.x, v1 - rb.y);
        }
        sv[R][C] = v;
    }
    __syncthreads();

    float2 vc = sv[ty + 1][tx + 1];
    float2 vu = sv[ty][tx + 1];
    float2 vl = sv[ty + 1][tx];
    float2 vd = sv[ty + 2][tx + 1];

    float G0 = vc.x - vu.x;
    float G1 = (w > 0) ? (vc.x - vl.x) : 0.f;
    float G2 = vc.y - vl.y;
    float G3 = (h < HH - 1) ? (vd.y - vc.y) : 0.f;

    float u0 = u2o.x + SIGMAc * G0;
    float u1 = u2o.y + SIGMAc * G1;
    float u2c = u2o.z + SIGMAc * G2;
    float u3 = u2o.w + SIGMAc * G3;

    float nrm = sqrtf(u0 * u0 + u1 * u1 + u2c * u2c + u3 * u3);
    float sc = 1.f / fmaxf(nrm * (1.f / lam2), 1.f);
    u0 *= sc; u1 *= sc; u2c *= sc; u3 *= sc;

    g_u2p[ip] = u2pack(u2o.x + RHOc * (u0  - u2o.x),
                       u2o.y + RHOc * (u1  - u2o.y),
                       u2o.z + RHOc * (u2c - u2o.z),
                       u2o.w + RHOc * (u3  - u2o.w));

    if (FIRST) {
        uint2 s;
        s.x = __float_as_uint(sx[ty + 1][tx + 1]);
        s.y = 0u;
        g_s[i] = s;
    }
    cudaTriggerProgrammaticLaunchCompletion();
}

// ---------------------------------------------------------------------------
// Host side: PDL launches on the default (capture) stream.
// ---------------------------------------------------------------------------
static void launch_pdl_A(void (*fn)(const float*, const int*, float*),
                         dim3 g, dim3 blk,
                         const float* y, const int* ths, float* out) {
    cudaLaunchConfig_t cfg = {};
    cfg.gridDim = g;
    cfg.blockDim = blk;
    cfg.dynamicSmemBytes = 0;
    cfg.stream = 0;
    cudaLaunchAttribute attr[1];
    attr[0].id = cudaLaunchAttributeProgrammaticStreamSerialization;
    attr[0].val.programmaticStreamSerializationAllowed = 1;
    cfg.attrs = attr;
    cfg.numAttrs = 1;
    cudaLaunchKernelEx(&cfg, fn, y, ths, out);
}
static void launch_pdl_B(void (*fn)(const float*, const int*), dim3 g, dim3 blk,
                         const float* y, const int* ths) {
    cudaLaunchConfig_t cfg = {};
    cfg.gridDim = g;
    cfg.blockDim = blk;
    cfg.dynamicSmemBytes = 0;
    cfg.stream = 0;
    cudaLaunchAttribute attr[1];
    attr[0].id = cudaLaunchAttributeProgrammaticStreamSerialization;
    attr[0].val.programmaticStreamSerializationAllowed = 1;
    cfg.attrs = attr;
    cfg.numAttrs = 1;
    cudaLaunchKernelEx(&cfg, fn, y, ths);
}

extern "C" void kernel_launch(void* const* d_in, const int* in_sizes, int n_in,
                              void* d_out, int out_size) {
    const float* y   = (const float*)d_in[0];
    const int*   ths = (const int*)d_in[1];
    float*       out = (float*)d_out;

    dim3 blkA(32, 8, 1);
    dim3 grdA(WW / 32, HH / 16, BB);     // 2 rows per thread
    dim3 blkB(TW, TH, 1);
    dim3 grdB(WW / TW, HH / TH, BB);

    // Iteration 1 (specialized: A is a no-op closed form)
    launch_pdl_B(k_B<true>, grdB, blkB, y, ths);

    // Iterations 2..9
    for (int it = 1; it < 9; ++it) {
        launch_pdl_A(k_A<false>, grdA, blkA, y, ths, nullptr);
        launch_pdl_B(k_B<false>, grdB, blkB, y, ths);
    }

    // Iteration 10: only the x path matters; write straight to output.
    launch_pdl_A(k_A<true>, grdA, blkA, y, ths, out);
}